// round 13
// baseline (speedup 1.0000x reference)
#include <cuda_runtime.h>
#include <cuda_fp16.h>
#include <cstdint>

#define MAXN 50000
#define MAXE 800000
#define SCAN_BLK 1024

// ---- scratch (static device globals; no allocation anywhere) ----
__device__ __half g_yl[MAXN * 128];     // aggregation operand (lin_l path), fp16
__device__ float  g_yr[MAXN * 128];     // residual path (Wr+Ws), fp32
__device__ __half g_h[MAXN * 128];      // hidden activations, fp16
__device__ __half g_wcat[640 * 128];    // B^T all 3 layers, fp16: [nc rows][128 K]
__device__ float  g_inv[MAXN];
__device__ int    g_deg[MAXN];          // zero-init at load; self-zeroed by scan each run
__device__ int    g_rowptr[MAXN + 1];
__device__ int    g_cursor[MAXN];
__device__ int    g_srcs[MAXE];
__device__ int    g_is64;
__device__ unsigned long long g_lb[64]; // lookback state: flag(2b hi) | value

// ================= fused setup: wcat + probe + lb-zero + cnt =================
#define WCAT_BLOCKS 320   // 640*128 / 256
__global__ void setup_kernel(const float* __restrict__ Wl0, const float* __restrict__ Wr0, const float* __restrict__ Ws0,
                             const float* __restrict__ Wl1, const float* __restrict__ Wr1, const float* __restrict__ Ws1,
                             const float* __restrict__ Wl2, const float* __restrict__ Wr2, const float* __restrict__ Ws2,
                             const void* __restrict__ ei, int E, int N) {
    int b = blockIdx.x;
    if (b < WCAT_BLOCKS) {
        int i = b * 256 + threadIdx.x;           // i = grow*128 + k
        int grow = i >> 7, k = i & 127;
        const float *Wl, *Wr, *Ws;
        int j, dout;
        if (grow < 256)      { Wl = Wl0; Wr = Wr0; Ws = Ws0; j = grow;       dout = 128; }
        else if (grow < 512) { Wl = Wl1; Wr = Wr1; Ws = Ws1; j = grow - 256; dout = 128; }
        else                 { Wl = Wl2; Wr = Wr2; Ws = Ws2; j = grow - 512; dout = 64;  }
        float v = (j < dout) ? Wl[k * dout + j]
                             : (Wr[k * dout + (j - dout)] + Ws[k * dout + (j - dout)]);
        g_wcat[i] = __float2half_rn(v);
    } else if (b == WCAT_BLOCKS) {
        __shared__ int s_bad;
        if (threadIdx.x == 0) s_bad = 0;
        __syncthreads();
        const long long* p = (const long long*)ei;
        int nprobe = (E < 1024) ? E : 1024;
        for (int i = threadIdx.x; i < nprobe; i += blockDim.x) {
            long long v = p[i];
            if (v < 0 || v >= (long long)N) s_bad = 1;
        }
        __syncthreads();
        if (threadIdx.x == 0) g_is64 = s_bad ? 0 : 1;
    } else if (b == WCAT_BLOCKS + 1) {
        if (threadIdx.x < 64) g_lb[threadIdx.x] = 0ull;
    } else {
        int base = ((b - WCAT_BLOCKS - 2) * 256 + threadIdx.x) * 4;
        if (base >= E) return;
        if (!g_is64 && (E & 3) == 0 && base + 4 <= E) {
            int4 d = *(const int4*)&((const int*)ei)[E + base];
            if (d.x >= 0 && d.x < N) atomicAdd(&g_deg[d.x], 1);
            if (d.y >= 0 && d.y < N) atomicAdd(&g_deg[d.y], 1);
            if (d.z >= 0 && d.z < N) atomicAdd(&g_deg[d.z], 1);
            if (d.w >= 0 && d.w < N) atomicAdd(&g_deg[d.w], 1);
        } else {
            for (int e = base; e < base + 4 && e < E; e++) {
                int dst = g_is64 ? (int)((const long long*)ei)[E + e] : ((const int*)ei)[E + e];
                if (dst >= 0 && dst < N) atomicAdd(&g_deg[dst], 1);
            }
        }
    }
}

__device__ __forceinline__ int edge_at(const void* ei, int E, int pos) {
    if (g_is64) return (int)((const long long*)ei)[pos];
    return ((const int*)ei)[pos];
}

// ================= single-pass scan with decoupled lookback =================
__device__ __forceinline__ int block_scan_incl(int v, int* warp_sums) {
    int lane = threadIdx.x & 31, wid = threadIdx.x >> 5;
    int x = v;
    #pragma unroll
    for (int o = 1; o < 32; o <<= 1) {
        int t = __shfl_up_sync(0xFFFFFFFFu, x, o);
        if (lane >= o) x += t;
    }
    if (lane == 31) warp_sums[wid] = x;
    __syncthreads();
    if (wid == 0) {
        int nw = (blockDim.x + 31) >> 5;
        int w = (lane < nw) ? warp_sums[lane] : 0;
        #pragma unroll
        for (int o = 1; o < 32; o <<= 1) {
            int t = __shfl_up_sync(0xFFFFFFFFu, w, o);
            if (lane >= o) w += t;
        }
        warp_sums[lane] = w;
    }
    __syncthreads();
    return x + (wid > 0 ? warp_sums[wid - 1] : 0);
}

__global__ __launch_bounds__(SCAN_BLK, 1)
void scan_lb_kernel(int n, int nb) {
    __shared__ int warp_sums[32];
    __shared__ int s_excl;
    const int b = blockIdx.x, tid = threadIdx.x;
    int i = b * SCAN_BLK + tid;
    int v = (i < n) ? g_deg[i] : 0;
    int incl = block_scan_incl(v, warp_sums);
    int total = warp_sums[31];

    if (tid < 32) {
        if (b == 0) {
            if (tid == 0) {
                atomicExch(&g_lb[0], (2ull << 62) | (unsigned)total);
                s_excl = 0;
            }
        } else {
            if (tid == 0)
                atomicExch(&g_lb[b], (1ull << 62) | (unsigned)total);
            int excl = 0;
            int base = b - 1;
            for (;;) {
                int idx = base - tid;
                unsigned long long w = 0ull;
                if (idx >= 0) {
                    volatile unsigned long long* p = &g_lb[idx];
                    do { w = *p; } while ((w >> 62) == 0ull);
                }
                unsigned flag = (idx >= 0) ? (unsigned)(w >> 62) : 1u;
                int val = (int)(unsigned)(w & 0xFFFFFFFFull);
                unsigned pre_mask = __ballot_sync(0xFFFFFFFFu, flag == 2u);
                if (pre_mask) {
                    int lstar = __ffs(pre_mask) - 1;
                    int contrib = (tid <= lstar) ? val : 0;
                    #pragma unroll
                    for (int o = 16; o > 0; o >>= 1)
                        contrib += __shfl_xor_sync(0xFFFFFFFFu, contrib, o);
                    excl += contrib;
                    break;
                } else {
                    int contrib = val;
                    #pragma unroll
                    for (int o = 16; o > 0; o >>= 1)
                        contrib += __shfl_xor_sync(0xFFFFFFFFu, contrib, o);
                    excl += contrib;
                    base -= 32;
                }
            }
            if (tid == 0) {
                atomicExch(&g_lb[b], (2ull << 62) | (unsigned)(excl + total));
                s_excl = excl;
            }
        }
    }
    __syncthreads();
    int excl = s_excl;
    if (i < n) {
        int r = (incl - v) + excl;
        g_rowptr[i] = r;
        g_cursor[i] = r;
        g_inv[i] = 1.0f / fmaxf((float)v, 1.0f);
        g_deg[i] = 0;              // self-restore for next run's fused cnt
    }
    if (b == nb - 1 && tid == SCAN_BLK - 1)
        g_rowptr[n] = excl + incl;
}

__global__ void fill_kernel(const void* __restrict__ ei, int E, int N) {
    int base = (blockIdx.x * blockDim.x + threadIdx.x) * 4;
    if (base >= E) return;
    if (!g_is64 && (E & 3) == 0 && base + 4 <= E) {
        const int* p = (const int*)ei;
        int4 s = *(const int4*)&p[base];
        int4 d = *(const int4*)&p[E + base];
        if (s.x >= 0 && s.x < N && d.x >= 0 && d.x < N) { int q = atomicAdd(&g_cursor[d.x], 1); if (q >= 0 && q < E) g_srcs[q] = s.x; }
        if (s.y >= 0 && s.y < N && d.y >= 0 && d.y < N) { int q = atomicAdd(&g_cursor[d.y], 1); if (q >= 0 && q < E) g_srcs[q] = s.y; }
        if (s.z >= 0 && s.z < N && d.z >= 0 && d.z < N) { int q = atomicAdd(&g_cursor[d.z], 1); if (q >= 0 && q < E) g_srcs[q] = s.z; }
        if (s.w >= 0 && s.w < N && d.w >= 0 && d.w < N) { int q = atomicAdd(&g_cursor[d.w], 1); if (q >= 0 && q < E) g_srcs[q] = s.w; }
    } else {
        for (int e = base; e < base + 4 && e < E; e++) {
            int src = edge_at(ei, E, e);
            int dst = edge_at(ei, E, E + e);
            if (src >= 0 && src < N && dst >= 0 && dst < N) {
                int q = atomicAdd(&g_cursor[dst], 1);
                if (q >= 0 && q < E) g_srcs[q] = src;
            }
        }
    }
}

// ================= fp16 mma.sync GEMM — 128x128 block tile, ldmatrix =================
#define HS 136
static constexpr int GSM_BYTES = (128 * HS + 128 * HS) * 2;  // 69632

__device__ __forceinline__ uint32_t smem_u32(const void* p) {
    uint32_t a;
    asm("{ .reg .u64 t; cvta.to.shared.u64 t, %1; cvt.u32.u64 %0, t; }" : "=r"(a) : "l"(p));
    return a;
}

__device__ __forceinline__ void ldsm_x4(uint32_t& r0, uint32_t& r1, uint32_t& r2, uint32_t& r3,
                                        uint32_t addr) {
    asm volatile("ldmatrix.sync.aligned.m8n8.x4.shared.b16 {%0,%1,%2,%3}, [%4];"
                 : "=r"(r0), "=r"(r1), "=r"(r2), "=r"(r3) : "r"(addr));
}

__device__ __forceinline__ void mma16n8k16(float* c, const uint32_t* a, const uint32_t* b) {
    asm volatile(
        "mma.sync.aligned.m16n8k16.row.col.f32.f16.f16.f32 "
        "{%0,%1,%2,%3}, {%4,%5,%6,%7}, {%8,%9}, {%0,%1,%2,%3};"
        : "+f"(c[0]), "+f"(c[1]), "+f"(c[2]), "+f"(c[3])
        : "r"(a[0]), "r"(a[1]), "r"(a[2]), "r"(a[3]), "r"(b[0]), "r"(b[1]));
}

// Block tile 128(M) x 128(N), full K=128 resident. 8 warps: 4(M) x 2(N).
// Warp tile 32x64 = 2 m16 tiles x 8 n8 tiles.
template <bool A32>
__global__ __launch_bounds__(256, 2)
void mma_gemm_kernel(const float* __restrict__ Ain, int M, int dout, int wrow0) {
    extern __shared__ __half sh[];
    __half* As = sh;              // [128][HS]
    __half* Bs = sh + 128 * HS;   // [128][HS]
    const int tid = threadIdx.x;
    const int warp = tid >> 5;
    const int lane = tid & 31;
    const int warpM = warp & 3;
    const int warpN = warp >> 2;
    const int row0 = blockIdx.x * 128;
    const int col0 = blockIdx.y * 128;

    // ---- load A tile (128 rows x 128 K) ----
    if (A32) {
        const float4* A4 = (const float4*)Ain;
        #pragma unroll
        for (int i = 0; i < 16; i++) {
            int idx = i * 256 + tid;
            int row = idx >> 5;
            int q   = idx & 31;
            float4 v = make_float4(0.f, 0.f, 0.f, 0.f);
            int gr = row0 + row;
            if (gr < M) v = A4[gr * 32 + q];
            __half2 h0 = __floats2half2_rn(v.x, v.y);
            __half2 h1 = __floats2half2_rn(v.z, v.w);
            *(uint2*)&As[row * HS + q * 4] =
                make_uint2(*(uint32_t*)&h0, *(uint32_t*)&h1);
        }
    } else {
        const uint4* H4 = (const uint4*)g_h;
        #pragma unroll
        for (int i = 0; i < 8; i++) {
            int idx = i * 256 + tid;
            int row = idx >> 4;
            int q   = idx & 15;
            uint4 v = make_uint4(0u, 0u, 0u, 0u);
            int gr = row0 + row;
            if (gr < M) v = H4[gr * 16 + q];
            *(uint2*)&As[row * HS + q * 8]     = make_uint2(v.x, v.y);
            *(uint2*)&As[row * HS + q * 8 + 4] = make_uint2(v.z, v.w);
        }
    }
    // ---- load B tile (128 rows x 128 halves) ----
    {
        const uint4* W4 = (const uint4*)g_wcat;
        #pragma unroll
        for (int i = 0; i < 8; i++) {
            int idx = i * 256 + tid;
            int row = idx >> 4;
            int q   = idx & 15;
            uint4 v = W4[(wrow0 + col0 + row) * 16 + q];
            *(uint2*)&Bs[row * HS + q * 8]     = make_uint2(v.x, v.y);
            *(uint2*)&Bs[row * HS + q * 8 + 4] = make_uint2(v.z, v.w);
        }
    }
    __syncthreads();

    float c[2][8][4];
    #pragma unroll
    for (int mt = 0; mt < 2; mt++)
        #pragma unroll
        for (int nt = 0; nt < 8; nt++)
            #pragma unroll
            for (int j = 0; j < 4; j++) c[mt][nt][j] = 0.f;

    const uint32_t as_b = smem_u32(As);
    const uint32_t bs_b = smem_u32(Bs);
    uint32_t aaddr0 = as_b + (uint32_t)(((warpM * 32 + (lane & 15)) * HS + ((lane >> 4) << 3)) << 1);
    uint32_t aaddr1 = aaddr0 + (uint32_t)((16 * HS) << 1);
    uint32_t baddr  = bs_b + (uint32_t)(((warpN * 64 + (lane & 7) + ((lane >> 4) << 3)) * HS
                                         + (((lane >> 3) & 1) << 3)) << 1);
    const uint32_t bstep = (uint32_t)((16 * HS) << 1);

    #pragma unroll
    for (int ks = 0; ks < 8; ks++) {
        const uint32_t ko = ks * 32;   // 16 halves = 32 bytes
        uint32_t a[2][4], b[8][2];
        ldsm_x4(a[0][0], a[0][1], a[0][2], a[0][3], aaddr0 + ko);
        ldsm_x4(a[1][0], a[1][1], a[1][2], a[1][3], aaddr1 + ko);
        ldsm_x4(b[0][0], b[0][1], b[1][0], b[1][1], baddr + ko);
        ldsm_x4(b[2][0], b[2][1], b[3][0], b[3][1], baddr + bstep + ko);
        ldsm_x4(b[4][0], b[4][1], b[5][0], b[5][1], baddr + 2 * bstep + ko);
        ldsm_x4(b[6][0], b[6][1], b[7][0], b[7][1], baddr + 3 * bstep + ko);
        #pragma unroll
        for (int mt = 0; mt < 2; mt++)
            #pragma unroll
            for (int nt = 0; nt < 8; nt++)
                mma16n8k16(c[mt][nt], a[mt], b[nt]);
    }

    // ---- epilogue (per-nt yl/yr split; nt tile spans 8 cols, dout % 64 == 0) ----
    #pragma unroll
    for (int mt = 0; mt < 2; mt++) {
        int r_lo = row0 + warpM * 32 + mt * 16 + (lane >> 2);
        #pragma unroll
        for (int nt = 0; nt < 8; nt++) {
            int col = col0 + warpN * 64 + nt * 8 + 2 * (lane & 3);
            if (col < dout) {
                if (r_lo < M)
                    *(__half2*)&g_yl[r_lo * dout + col] =
                        __floats2half2_rn(c[mt][nt][0], c[mt][nt][1]);
                if (r_lo + 8 < M)
                    *(__half2*)&g_yl[(r_lo + 8) * dout + col] =
                        __floats2half2_rn(c[mt][nt][2], c[mt][nt][3]);
            } else {
                int cc = col - dout;
                if (r_lo < M)
                    *(float2*)&g_yr[r_lo * dout + cc] = make_float2(c[mt][nt][0], c[mt][nt][1]);
                if (r_lo + 8 < M)
                    *(float2*)&g_yr[(r_lo + 8) * dout + cc] = make_float2(c[mt][nt][2], c[mt][nt][3]);
            }
        }
    }
}

// ================= fused aggregation epilogue =================
__device__ __forceinline__ void add4h(float* a, uint2 u) {
    __half2 h0 = *(__half2*)&u.x;
    __half2 h1 = *(__half2*)&u.y;
    float2 f0 = __half22float2(h0);
    float2 f1 = __half22float2(h1);
    a[0] += f0.x; a[1] += f0.y; a[2] += f1.x; a[3] += f1.y;
}

// OUT16: write g_h (fp16, with relu); else write outp (fp32, no relu)
template <int DOUT, bool OUT16>
__global__ void agg_kernel(const float* __restrict__ bl, const float* __restrict__ bs,
                           float* __restrict__ outp, int N) {
    const int HQ = DOUT / 4;
    int gt = blockIdx.x * blockDim.x + threadIdx.x;
    int n  = gt / HQ;
    int q  = gt & (HQ - 1);
    if (n >= N) return;

    int beg = g_rowptr[n];
    int end = g_rowptr[n + 1];
    const uint2* YL = (const uint2*)g_yl;

    float a0[4] = {0.f, 0.f, 0.f, 0.f};
    float a1[4] = {0.f, 0.f, 0.f, 0.f};
    float a2[4] = {0.f, 0.f, 0.f, 0.f};
    float a3[4] = {0.f, 0.f, 0.f, 0.f};
    int j = beg;
    for (; j + 3 < end; j += 4) {
        uint2 u0 = YL[g_srcs[j]     * HQ + q];
        uint2 u1 = YL[g_srcs[j + 1] * HQ + q];
        uint2 u2 = YL[g_srcs[j + 2] * HQ + q];
        uint2 u3 = YL[g_srcs[j + 3] * HQ + q];
        add4h(a0, u0); add4h(a1, u1); add4h(a2, u2); add4h(a3, u3);
    }
    for (; j < end; j++) add4h(a0, YL[g_srcs[j] * HQ + q]);
    #pragma unroll
    for (int k = 0; k < 4; k++) a0[k] += (a1[k] + a2[k]) + a3[k];

    float inv = g_inv[n];
    float4 yr = ((const float4*)g_yr)[n * HQ + q];
    float4 b1 = ((const float4*)bl)[q];
    float4 b2 = ((const float4*)bs)[q];
    float4 o;
    o.x = fmaf(a0[0], inv, yr.x) + b1.x + b2.x;
    o.y = fmaf(a0[1], inv, yr.y) + b1.y + b2.y;
    o.z = fmaf(a0[2], inv, yr.z) + b1.z + b2.z;
    o.w = fmaf(a0[3], inv, yr.w) + b1.w + b2.w;
    if (OUT16) {
        o.x = fmaxf(o.x, 0.f); o.y = fmaxf(o.y, 0.f);
        o.z = fmaxf(o.z, 0.f); o.w = fmaxf(o.w, 0.f);
        __half2 h0 = __floats2half2_rn(o.x, o.y);
        __half2 h1 = __floats2half2_rn(o.z, o.w);
        *(uint2*)&g_h[n * DOUT + q * 4] = make_uint2(*(uint32_t*)&h0, *(uint32_t*)&h1);
    } else {
        ((float4*)outp)[n * HQ + q] = o;
    }
}

// ================= host launch =================
extern "C" void kernel_launch(void* const* d_in, const int* in_sizes, int n_in,
                              void* d_out, int out_size) {
    const float* x  = (const float*)d_in[0];
    const void*  ei = d_in[1];
    const float* Wl[3] = {(const float*)d_in[4],  (const float*)d_in[9],  (const float*)d_in[14]};
    const float* bl[3] = {(const float*)d_in[5],  (const float*)d_in[10], (const float*)d_in[15]};
    const float* Wr[3] = {(const float*)d_in[6],  (const float*)d_in[11], (const float*)d_in[16]};
    const float* Ws[3] = {(const float*)d_in[7],  (const float*)d_in[12], (const float*)d_in[17]};
    const float* bs[3] = {(const float*)d_in[8],  (const float*)d_in[13], (const float*)d_in[18]};

    int N = in_sizes[0] / 128;
    int E = in_sizes[1] / 2;

    cudaFuncSetAttribute(mma_gemm_kernel<true>,  cudaFuncAttributeMaxDynamicSharedMemorySize, GSM_BYTES);
    cudaFuncSetAttribute(mma_gemm_kernel<false>, cudaFuncAttributeMaxDynamicSharedMemorySize, GSM_BYTES);

    // ---- setup (wcat + probe + lb-zero + cnt) ----
    int egrid = (E / 4 + 255) / 256;
    setup_kernel<<<WCAT_BLOCKS + 2 + egrid, 256>>>(Wl[0], Wr[0], Ws[0], Wl[1], Wr[1], Ws[1],
                                                   Wl[2], Wr[2], Ws[2], ei, E, N);
    // ---- single-pass scan + fill ----
    int nb = (N + SCAN_BLK - 1) / SCAN_BLK;
    scan_lb_kernel<<<nb, SCAN_BLK>>>(N, nb);
    fill_kernel<<<(E / 4 + 255) / 256, 256>>>(ei, E, N);

    const int douts[3]  = {128, 128, 64};
    const int wrow0s[3] = {0, 256, 512};
    for (int L = 0; L < 3; L++) {
        int dout = douts[L];
        int nc   = 2 * dout;

        dim3 gg((N + 127) / 128, nc / 128);
        if (L == 0)
            mma_gemm_kernel<true><<<gg, 256, GSM_BYTES>>>(x, N, dout, wrow0s[L]);
        else
            mma_gemm_kernel<false><<<gg, 256, GSM_BYTES>>>(nullptr, N, dout, wrow0s[L]);

        int threads = N * (dout / 4);
        if (L < 2)
            agg_kernel<128, true><<<(threads + 255) / 256, 256>>>(bl[L], bs[L], nullptr, N);
        else
            agg_kernel<64, false><<<(threads + 255) / 256, 256>>>(bl[L], bs[L], (float*)d_out, N);
    }
}

// round 14
// speedup vs baseline: 1.4220x; 1.4220x over previous
#include <cuda_runtime.h>
#include <cuda_fp16.h>
#include <cstdint>

#define MAXN 50000
#define MAXE 800000
#define SCAN_BLK 1024
#define NBLK_SCAN ((MAXN + SCAN_BLK - 1) / SCAN_BLK)

// ---- scratch (static device globals; no allocation anywhere) ----
__device__ __half g_yl[MAXN * 128];     // aggregation operand (lin_l path), fp16
__device__ float  g_yr[MAXN * 128];     // residual path (Wr+Ws), fp32
__device__ __half g_h[MAXN * 128];      // hidden activations, fp16
__device__ __half g_wcat[640 * 128];    // B^T all 3 layers, fp16: [nc rows][128 K]
__device__ float  g_inv[MAXN];
__device__ int    g_deg[MAXN];
__device__ int    g_rowptr[MAXN + 1];
__device__ int    g_cursor[MAXN];
__device__ int    g_srcs[MAXE];
__device__ int    g_is64;
__device__ int    g_bsum[NBLK_SCAN + 1];

// ================= fused setup: wcat (fp16) + zero_deg + dtype probe =================
#define WCAT_BLOCKS 320   // 640*128 / 256
__global__ void setup_kernel(const float* __restrict__ Wl0, const float* __restrict__ Wr0, const float* __restrict__ Ws0,
                             const float* __restrict__ Wl1, const float* __restrict__ Wr1, const float* __restrict__ Ws1,
                             const float* __restrict__ Wl2, const float* __restrict__ Wr2, const float* __restrict__ Ws2,
                             const void* __restrict__ ei, int E, int N) {
    int b = blockIdx.x;
    if (b < WCAT_BLOCKS) {
        int i = b * 256 + threadIdx.x;           // i = grow*128 + k
        int grow = i >> 7, k = i & 127;
        const float *Wl, *Wr, *Ws;
        int j, dout;
        if (grow < 256)      { Wl = Wl0; Wr = Wr0; Ws = Ws0; j = grow;       dout = 128; }
        else if (grow < 512) { Wl = Wl1; Wr = Wr1; Ws = Ws1; j = grow - 256; dout = 128; }
        else                 { Wl = Wl2; Wr = Wr2; Ws = Ws2; j = grow - 512; dout = 64;  }
        float v = (j < dout) ? Wl[k * dout + j]
                             : (Wr[k * dout + (j - dout)] + Ws[k * dout + (j - dout)]);
        g_wcat[i] = __float2half_rn(v);
    } else if (b < gridDim.x - 1) {
        int i = (b - WCAT_BLOCKS) * 256 + threadIdx.x;
        if (i < N) g_deg[i] = 0;
    } else {
        __shared__ int s_bad;
        if (threadIdx.x == 0) s_bad = 0;
        __syncthreads();
        const long long* p = (const long long*)ei;
        int nprobe = (E < 1024) ? E : 1024;
        for (int i = threadIdx.x; i < nprobe; i += blockDim.x) {
            long long v = p[i];
            if (v < 0 || v >= (long long)N) s_bad = 1;
        }
        __syncthreads();
        if (threadIdx.x == 0) g_is64 = s_bad ? 0 : 1;
    }
}

__device__ __forceinline__ int edge_at(const void* ei, int E, int pos) {
    if (g_is64) return (int)((const long long*)ei)[pos];
    return ((const int*)ei)[pos];
}

// ================= scan (R8 3-phase) =================
__device__ __forceinline__ int block_scan_incl(int v, int* warp_sums) {
    int lane = threadIdx.x & 31, wid = threadIdx.x >> 5;
    int x = v;
    #pragma unroll
    for (int o = 1; o < 32; o <<= 1) {
        int t = __shfl_up_sync(0xFFFFFFFFu, x, o);
        if (lane >= o) x += t;
    }
    if (lane == 31) warp_sums[wid] = x;
    __syncthreads();
    if (wid == 0) {
        int nw = (blockDim.x + 31) >> 5;
        int w = (lane < nw) ? warp_sums[lane] : 0;
        #pragma unroll
        for (int o = 1; o < 32; o <<= 1) {
            int t = __shfl_up_sync(0xFFFFFFFFu, w, o);
            if (lane >= o) w += t;
        }
        warp_sums[lane] = w;
    }
    __syncthreads();
    return x + (wid > 0 ? warp_sums[wid - 1] : 0);
}

__global__ __launch_bounds__(SCAN_BLK, 1)
void scan1_kernel(int n) {
    __shared__ int warp_sums[32];
    int i = blockIdx.x * SCAN_BLK + threadIdx.x;
    int v = (i < n) ? g_deg[i] : 0;
    int incl = block_scan_incl(v, warp_sums);
    if (i < n) g_rowptr[i] = incl - v;
    if (threadIdx.x == SCAN_BLK - 1) g_bsum[blockIdx.x] = incl;
}

__global__ __launch_bounds__(SCAN_BLK, 1)
void scan2_kernel(int nb) {
    __shared__ int warp_sums[32];
    int t = threadIdx.x;
    int v = (t < nb) ? g_bsum[t] : 0;
    int incl = block_scan_incl(v, warp_sums);
    if (t < nb) g_bsum[t] = incl - v;
    if (t == nb - 1) g_bsum[nb] = incl;
}

__global__ __launch_bounds__(SCAN_BLK, 1)
void scan3_kernel(int n) {
    int i = blockIdx.x * SCAN_BLK + threadIdx.x;
    if (i < n) {
        int r = g_rowptr[i] + g_bsum[blockIdx.x];
        g_rowptr[i] = r;
        g_cursor[i] = r;
        g_inv[i] = 1.0f / fmaxf((float)g_deg[i], 1.0f);
    }
    if (blockIdx.x == 0 && threadIdx.x == 0)
        g_rowptr[n] = g_bsum[(n + SCAN_BLK - 1) / SCAN_BLK];
}

__global__ void fill_kernel(const void* __restrict__ ei, int E, int N) {
    int base = (blockIdx.x * blockDim.x + threadIdx.x) * 4;
    if (base >= E) return;
    if (!g_is64 && (E & 3) == 0 && base + 4 <= E) {
        const int* p = (const int*)ei;
        int4 s = *(const int4*)&p[base];
        int4 d = *(const int4*)&p[E + base];
        if (s.x >= 0 && s.x < N && d.x >= 0 && d.x < N) { int q = atomicAdd(&g_cursor[d.x], 1); if (q >= 0 && q < E) g_srcs[q] = s.x; }
        if (s.y >= 0 && s.y < N && d.y >= 0 && d.y < N) { int q = atomicAdd(&g_cursor[d.y], 1); if (q >= 0 && q < E) g_srcs[q] = s.y; }
        if (s.z >= 0 && s.z < N && d.z >= 0 && d.z < N) { int q = atomicAdd(&g_cursor[d.z], 1); if (q >= 0 && q < E) g_srcs[q] = s.z; }
        if (s.w >= 0 && s.w < N && d.w >= 0 && d.w < N) { int q = atomicAdd(&g_cursor[d.w], 1); if (q >= 0 && q < E) g_srcs[q] = s.w; }
    } else {
        for (int e = base; e < base + 4 && e < E; e++) {
            int src = edge_at(ei, E, e);
            int dst = edge_at(ei, E, E + e);
            if (src >= 0 && src < N && dst >= 0 && dst < N) {
                int q = atomicAdd(&g_cursor[dst], 1);
                if (q >= 0 && q < E) g_srcs[q] = src;
            }
        }
    }
}

// ================= fp16 mma.sync GEMM (R8 config) + fused cnt blocks =================
// Blocks with blockIdx.x >= gemmx (and y==0, ei != nullptr) run the degree count
// instead of GEMM work — hides cnt inside the layer-0 GEMM wave.
#define HS 136
static constexpr int GSM_BYTES = (128 * HS + 64 * HS) * 2;  // 52224

__device__ __forceinline__ void mma16n8k16(float* c, const uint32_t* a, const uint32_t* b) {
    asm volatile(
        "mma.sync.aligned.m16n8k16.row.col.f32.f16.f16.f32 "
        "{%0,%1,%2,%3}, {%4,%5,%6,%7}, {%8,%9}, {%0,%1,%2,%3};"
        : "+f"(c[0]), "+f"(c[1]), "+f"(c[2]), "+f"(c[3])
        : "r"(a[0]), "r"(a[1]), "r"(a[2]), "r"(a[3]), "r"(b[0]), "r"(b[1]));
}

template <bool A32>
__global__ __launch_bounds__(256, 2)
void mma_gemm_kernel(const float* __restrict__ Ain, int M, int dout, int wrow0,
                     const void* __restrict__ ei, int E, int N, int gemmx) {
    if (blockIdx.x >= gemmx) {
        if (blockIdx.y == 0 && ei) {
            int base = ((blockIdx.x - gemmx) * 256 + threadIdx.x) * 4;
            if (base >= E) return;
            if (!g_is64 && (E & 3) == 0 && base + 4 <= E) {
                int4 d = *(const int4*)&((const int*)ei)[E + base];
                if (d.x >= 0 && d.x < N) atomicAdd(&g_deg[d.x], 1);
                if (d.y >= 0 && d.y < N) atomicAdd(&g_deg[d.y], 1);
                if (d.z >= 0 && d.z < N) atomicAdd(&g_deg[d.z], 1);
                if (d.w >= 0 && d.w < N) atomicAdd(&g_deg[d.w], 1);
            } else {
                for (int e = base; e < base + 4 && e < E; e++) {
                    int dst = g_is64 ? (int)((const long long*)ei)[E + e] : ((const int*)ei)[E + e];
                    if (dst >= 0 && dst < N) atomicAdd(&g_deg[dst], 1);
                }
            }
        }
        return;
    }

    extern __shared__ __half sh[];
    __half* As = sh;              // [128][HS]
    __half* Bs = sh + 128 * HS;   // [64][HS]
    const int tid = threadIdx.x;
    const int warp = tid >> 5;
    const int lane = tid & 31;
    const int warpM = warp & 3;
    const int warpN = warp >> 2;
    const int row0 = blockIdx.x * 128;
    const int col0 = blockIdx.y * 64;

    // ---- load A tile ----
    if (A32) {
        const float4* A4 = (const float4*)Ain;
        #pragma unroll
        for (int i = 0; i < 16; i++) {
            int idx = i * 256 + tid;
            int row = idx >> 5;
            int q   = idx & 31;
            float4 v = make_float4(0.f, 0.f, 0.f, 0.f);
            int gr = row0 + row;
            if (gr < M) v = A4[gr * 32 + q];
            __half2 h0 = __floats2half2_rn(v.x, v.y);
            __half2 h1 = __floats2half2_rn(v.z, v.w);
            *(uint2*)&As[row * HS + q * 4] =
                make_uint2(*(uint32_t*)&h0, *(uint32_t*)&h1);
        }
    } else {
        const uint4* H4 = (const uint4*)g_h;     // 8 halves per uint4
        #pragma unroll
        for (int i = 0; i < 8; i++) {
            int idx = i * 256 + tid;
            int row = idx >> 4;
            int q   = idx & 15;
            uint4 v = make_uint4(0u, 0u, 0u, 0u);
            int gr = row0 + row;
            if (gr < M) v = H4[gr * 16 + q];
            *(uint2*)&As[row * HS + q * 8]     = make_uint2(v.x, v.y);
            *(uint2*)&As[row * HS + q * 8 + 4] = make_uint2(v.z, v.w);
        }
    }
    // ---- load B tile (64 rows x 128 halves) ----
    {
        const uint4* W4 = (const uint4*)g_wcat;
        #pragma unroll
        for (int i = 0; i < 4; i++) {
            int idx = i * 256 + tid;
            int row = idx >> 4;
            int q   = idx & 15;
            uint4 v = W4[(wrow0 + col0 + row) * 16 + q];
            *(uint2*)&Bs[row * HS + q * 8]     = make_uint2(v.x, v.y);
            *(uint2*)&Bs[row * HS + q * 8 + 4] = make_uint2(v.z, v.w);
        }
    }
    __syncthreads();

    float c[2][4][4];
    #pragma unroll
    for (int mt = 0; mt < 2; mt++)
        #pragma unroll
        for (int nt = 0; nt < 4; nt++)
            #pragma unroll
            for (int j = 0; j < 4; j++) c[mt][nt][j] = 0.f;

    const int rA = warpM * 32 + (lane >> 2);
    const int nB = warpN * 32 + (lane >> 2);
    const int kh = (lane & 3) * 2;

    #pragma unroll
    for (int ks = 0; ks < 8; ks++) {
        const int k0 = ks * 16 + kh;
        uint32_t a[2][4], b[4][2];
        #pragma unroll
        for (int mt = 0; mt < 2; mt++) {
            int r = rA + mt * 16;
            a[mt][0] = *(const uint32_t*)&As[r * HS + k0];
            a[mt][1] = *(const uint32_t*)&As[(r + 8) * HS + k0];
            a[mt][2] = *(const uint32_t*)&As[r * HS + k0 + 8];
            a[mt][3] = *(const uint32_t*)&As[(r + 8) * HS + k0 + 8];
        }
        #pragma unroll
        for (int nt = 0; nt < 4; nt++) {
            int n = nB + nt * 8;
            b[nt][0] = *(const uint32_t*)&Bs[n * HS + k0];
            b[nt][1] = *(const uint32_t*)&Bs[n * HS + k0 + 8];
        }
        #pragma unroll
        for (int mt = 0; mt < 2; mt++)
            #pragma unroll
            for (int nt = 0; nt < 4; nt++)
                mma16n8k16(c[mt][nt], a[mt], b[nt]);
    }

    // ---- epilogue ----
    const bool isl = (col0 < dout);
    #pragma unroll
    for (int mt = 0; mt < 2; mt++) {
        int r_lo = row0 + warpM * 32 + mt * 16 + (lane >> 2);
        #pragma unroll
        for (int nt = 0; nt < 4; nt++) {
            int col = col0 + warpN * 32 + nt * 8 + 2 * (lane & 3);
            if (isl) {
                if (r_lo < M)
                    *(__half2*)&g_yl[r_lo * dout + col] =
                        __floats2half2_rn(c[mt][nt][0], c[mt][nt][1]);
                if (r_lo + 8 < M)
                    *(__half2*)&g_yl[(r_lo + 8) * dout + col] =
                        __floats2half2_rn(c[mt][nt][2], c[mt][nt][3]);
            } else {
                int cc = col - dout;
                if (r_lo < M)
                    *(float2*)&g_yr[r_lo * dout + cc] = make_float2(c[mt][nt][0], c[mt][nt][1]);
                if (r_lo + 8 < M)
                    *(float2*)&g_yr[(r_lo + 8) * dout + cc] = make_float2(c[mt][nt][2], c[mt][nt][3]);
            }
        }
    }
}

// ================= fused aggregation epilogue (R8 unroll-2) =================
__device__ __forceinline__ void add4h(float* a, uint2 u) {
    __half2 h0 = *(__half2*)&u.x;
    __half2 h1 = *(__half2*)&u.y;
    float2 f0 = __half22float2(h0);
    float2 f1 = __half22float2(h1);
    a[0] += f0.x; a[1] += f0.y; a[2] += f1.x; a[3] += f1.y;
}

// OUT16: write g_h (fp16, with relu); else write outp (fp32, no relu)
template <int DOUT, bool OUT16>
__global__ void agg_kernel(const float* __restrict__ bl, const float* __restrict__ bs,
                           float* __restrict__ outp, int N) {
    const int HQ = DOUT / 4;
    int gt = blockIdx.x * blockDim.x + threadIdx.x;
    int n  = gt / HQ;
    int q  = gt & (HQ - 1);
    if (n >= N) return;

    int beg = g_rowptr[n];
    int end = g_rowptr[n + 1];
    const uint2* YL = (const uint2*)g_yl;

    float a0[4] = {0.f, 0.f, 0.f, 0.f};
    float a1[4] = {0.f, 0.f, 0.f, 0.f};
    int j = beg;
    for (; j + 1 < end; j += 2) {
        uint2 u0 = YL[g_srcs[j] * HQ + q];
        uint2 u1 = YL[g_srcs[j + 1] * HQ + q];
        add4h(a0, u0);
        add4h(a1, u1);
    }
    if (j < end) add4h(a0, YL[g_srcs[j] * HQ + q]);
    #pragma unroll
    for (int k = 0; k < 4; k++) a0[k] += a1[k];

    float inv = g_inv[n];
    float4 yr = ((const float4*)g_yr)[n * HQ + q];
    float4 b1 = ((const float4*)bl)[q];
    float4 b2 = ((const float4*)bs)[q];
    float4 o;
    o.x = fmaf(a0[0], inv, yr.x) + b1.x + b2.x;
    o.y = fmaf(a0[1], inv, yr.y) + b1.y + b2.y;
    o.z = fmaf(a0[2], inv, yr.z) + b1.z + b2.z;
    o.w = fmaf(a0[3], inv, yr.w) + b1.w + b2.w;
    if (OUT16) {
        o.x = fmaxf(o.x, 0.f); o.y = fmaxf(o.y, 0.f);
        o.z = fmaxf(o.z, 0.f); o.w = fmaxf(o.w, 0.f);
        __half2 h0 = __floats2half2_rn(o.x, o.y);
        __half2 h1 = __floats2half2_rn(o.z, o.w);
        *(uint2*)&g_h[n * DOUT + q * 4] = make_uint2(*(uint32_t*)&h0, *(uint32_t*)&h1);
    } else {
        ((float4*)outp)[n * HQ + q] = o;
    }
}

// ================= host launch =================
extern "C" void kernel_launch(void* const* d_in, const int* in_sizes, int n_in,
                              void* d_out, int out_size) {
    const float* x  = (const float*)d_in[0];
    const void*  ei = d_in[1];
    const float* Wl[3] = {(const float*)d_in[4],  (const float*)d_in[9],  (const float*)d_in[14]};
    const float* bl[3] = {(const float*)d_in[5],  (const float*)d_in[10], (const float*)d_in[15]};
    const float* Wr[3] = {(const float*)d_in[6],  (const float*)d_in[11], (const float*)d_in[16]};
    const float* Ws[3] = {(const float*)d_in[7],  (const float*)d_in[12], (const float*)d_in[17]};
    const float* bs[3] = {(const float*)d_in[8],  (const float*)d_in[13], (const float*)d_in[18]};

    int N = in_sizes[0] / 128;
    int E = in_sizes[1] / 2;

    cudaFuncSetAttribute(mma_gemm_kernel<true>,  cudaFuncAttributeMaxDynamicSharedMemorySize, GSM_BYTES);
    cudaFuncSetAttribute(mma_gemm_kernel<false>, cudaFuncAttributeMaxDynamicSharedMemorySize, GSM_BYTES);

    // ---- setup (wcat + zero_deg + probe) ----
    int setup_grid = WCAT_BLOCKS + (N + 255) / 256 + 1;
    setup_kernel<<<setup_grid, 256>>>(Wl[0], Wr[0], Ws[0], Wl[1], Wr[1], Ws[1],
                                      Wl[2], Wr[2], Ws[2], ei, E, N);

    const int douts[3]  = {128, 128, 64};
    const int wrow0s[3] = {0, 256, 512};
    int gx = (N + 127) / 128;
    int cntb = (E / 4 + 255) / 256;

    // ---- layer 0 GEMM with fused cnt blocks ----
    {
        dim3 gg(gx + cntb, (2 * douts[0]) / 64);
        mma_gemm_kernel<true><<<gg, 256, GSM_BYTES>>>(x, N, douts[0], wrow0s[0],
                                                      ei, E, N, gx);
    }
    // ---- scan + fill (overlap-free remainder of CSR build) ----
    int nb = (N + SCAN_BLK - 1) / SCAN_BLK;
    scan1_kernel<<<nb, SCAN_BLK>>>(N);
    scan2_kernel<<<1, SCAN_BLK>>>(nb);
    scan3_kernel<<<nb, SCAN_BLK>>>(N);
    fill_kernel<<<(E / 4 + 255) / 256, 256>>>(ei, E, N);

    // ---- layer 0 agg, then layers 1..2 ----
    agg_kernel<128, true><<<(N * 32 + 255) / 256, 256>>>(bl[0], bs[0], nullptr, N);

    for (int L = 1; L < 3; L++) {
        int dout = douts[L];
        dim3 gg(gx, (2 * dout) / 64);
        mma_gemm_kernel<false><<<gg, 256, GSM_BYTES>>>(nullptr, N, dout, wrow0s[L],
                                                       nullptr, 0, N, gx);
        int threads = N * (dout / 4);
        if (L < 2)
            agg_kernel<128, true><<<(threads + 255) / 256, 256>>>(bl[L], bs[L], nullptr, N);
        else
            agg_kernel<64, false><<<(threads + 255) / 256, 256>>>(bl[L], bs[L], (float*)d_out, N);
    }
}

// round 15
// speedup vs baseline: 1.4596x; 1.0264x over previous
#include <cuda_runtime.h>
#include <cuda_fp16.h>
#include <cstdint>

#define MAXN 50000
#define MAXE 800000
#define SCAN_BLK 1024
#define NBLK_SCAN ((MAXN + SCAN_BLK - 1) / SCAN_BLK)

// ---- scratch (static device globals; no allocation anywhere) ----
__device__ __half g_yl[MAXN * 128];     // aggregation operand (lin_l path), fp16
__device__ __half g_yr[MAXN * 128];     // residual path (Wr+Ws), fp16
__device__ __half g_h[MAXN * 128];      // hidden activations, fp16
__device__ __half g_wcat[640 * 128];    // B^T all 3 layers, fp16: [nc rows][128 K]
__device__ float  g_inv[MAXN];
__device__ int    g_deg[MAXN];
__device__ int    g_rowptr[MAXN + 1];
__device__ int    g_cursor[MAXN];
__device__ int    g_srcs[MAXE];
__device__ int    g_is64;
__device__ int    g_bsum[NBLK_SCAN + 1];

// ================= fused setup: wcat (fp16) + zero_deg + dtype probe =================
#define WCAT_BLOCKS 320   // 640*128 / 256
__global__ void setup_kernel(const float* __restrict__ Wl0, const float* __restrict__ Wr0, const float* __restrict__ Ws0,
                             const float* __restrict__ Wl1, const float* __restrict__ Wr1, const float* __restrict__ Ws1,
                             const float* __restrict__ Wl2, const float* __restrict__ Wr2, const float* __restrict__ Ws2,
                             const void* __restrict__ ei, int E, int N) {
    int b = blockIdx.x;
    if (b < WCAT_BLOCKS) {
        int i = b * 256 + threadIdx.x;           // i = grow*128 + k
        int grow = i >> 7, k = i & 127;
        const float *Wl, *Wr, *Ws;
        int j, dout;
        if (grow < 256)      { Wl = Wl0; Wr = Wr0; Ws = Ws0; j = grow;       dout = 128; }
        else if (grow < 512) { Wl = Wl1; Wr = Wr1; Ws = Ws1; j = grow - 256; dout = 128; }
        else                 { Wl = Wl2; Wr = Wr2; Ws = Ws2; j = grow - 512; dout = 64;  }
        float v = (j < dout) ? Wl[k * dout + j]
                             : (Wr[k * dout + (j - dout)] + Ws[k * dout + (j - dout)]);
        g_wcat[i] = __float2half_rn(v);
    } else if (b < gridDim.x - 1) {
        int i = (b - WCAT_BLOCKS) * 256 + threadIdx.x;
        if (i < N) g_deg[i] = 0;
    } else {
        __shared__ int s_bad;
        if (threadIdx.x == 0) s_bad = 0;
        __syncthreads();
        const long long* p = (const long long*)ei;
        int nprobe = (E < 1024) ? E : 1024;
        for (int i = threadIdx.x; i < nprobe; i += blockDim.x) {
            long long v = p[i];
            if (v < 0 || v >= (long long)N) s_bad = 1;
        }
        __syncthreads();
        if (threadIdx.x == 0) g_is64 = s_bad ? 0 : 1;
    }
}

__device__ __forceinline__ int edge_at(const void* ei, int E, int pos) {
    if (g_is64) return (int)((const long long*)ei)[pos];
    return ((const int*)ei)[pos];
}

// ================= scan (R8 3-phase) =================
__device__ __forceinline__ int block_scan_incl(int v, int* warp_sums) {
    int lane = threadIdx.x & 31, wid = threadIdx.x >> 5;
    int x = v;
    #pragma unroll
    for (int o = 1; o < 32; o <<= 1) {
        int t = __shfl_up_sync(0xFFFFFFFFu, x, o);
        if (lane >= o) x += t;
    }
    if (lane == 31) warp_sums[wid] = x;
    __syncthreads();
    if (wid == 0) {
        int nw = (blockDim.x + 31) >> 5;
        int w = (lane < nw) ? warp_sums[lane] : 0;
        #pragma unroll
        for (int o = 1; o < 32; o <<= 1) {
            int t = __shfl_up_sync(0xFFFFFFFFu, w, o);
            if (lane >= o) w += t;
        }
        warp_sums[lane] = w;
    }
    __syncthreads();
    return x + (wid > 0 ? warp_sums[wid - 1] : 0);
}

__global__ __launch_bounds__(SCAN_BLK, 1)
void scan1_kernel(int n) {
    __shared__ int warp_sums[32];
    int i = blockIdx.x * SCAN_BLK + threadIdx.x;
    int v = (i < n) ? g_deg[i] : 0;
    int incl = block_scan_incl(v, warp_sums);
    if (i < n) g_rowptr[i] = incl - v;
    if (threadIdx.x == SCAN_BLK - 1) g_bsum[blockIdx.x] = incl;
}

__global__ __launch_bounds__(SCAN_BLK, 1)
void scan2_kernel(int nb) {
    __shared__ int warp_sums[32];
    int t = threadIdx.x;
    int v = (t < nb) ? g_bsum[t] : 0;
    int incl = block_scan_incl(v, warp_sums);
    if (t < nb) g_bsum[t] = incl - v;
    if (t == nb - 1) g_bsum[nb] = incl;
}

__global__ __launch_bounds__(SCAN_BLK, 1)
void scan3_kernel(int n) {
    int i = blockIdx.x * SCAN_BLK + threadIdx.x;
    if (i < n) {
        int r = g_rowptr[i] + g_bsum[blockIdx.x];
        g_rowptr[i] = r;
        g_cursor[i] = r;
        g_inv[i] = 1.0f / fmaxf((float)g_deg[i], 1.0f);
    }
    if (blockIdx.x == 0 && threadIdx.x == 0)
        g_rowptr[n] = g_bsum[(n + SCAN_BLK - 1) / SCAN_BLK];
}

__global__ void fill_kernel(const void* __restrict__ ei, int E, int N) {
    int base = (blockIdx.x * blockDim.x + threadIdx.x) * 4;
    if (base >= E) return;
    if (!g_is64 && (E & 3) == 0 && base + 4 <= E) {
        const int* p = (const int*)ei;
        int4 s = *(const int4*)&p[base];
        int4 d = *(const int4*)&p[E + base];
        if (s.x >= 0 && s.x < N && d.x >= 0 && d.x < N) { int q = atomicAdd(&g_cursor[d.x], 1); if (q >= 0 && q < E) g_srcs[q] = s.x; }
        if (s.y >= 0 && s.y < N && d.y >= 0 && d.y < N) { int q = atomicAdd(&g_cursor[d.y], 1); if (q >= 0 && q < E) g_srcs[q] = s.y; }
        if (s.z >= 0 && s.z < N && d.z >= 0 && d.z < N) { int q = atomicAdd(&g_cursor[d.z], 1); if (q >= 0 && q < E) g_srcs[q] = s.z; }
        if (s.w >= 0 && s.w < N && d.w >= 0 && d.w < N) { int q = atomicAdd(&g_cursor[d.w], 1); if (q >= 0 && q < E) g_srcs[q] = s.w; }
    } else {
        for (int e = base; e < base + 4 && e < E; e++) {
            int src = edge_at(ei, E, e);
            int dst = edge_at(ei, E, E + e);
            if (src >= 0 && src < N && dst >= 0 && dst < N) {
                int q = atomicAdd(&g_cursor[dst], 1);
                if (q >= 0 && q < E) g_srcs[q] = src;
            }
        }
    }
}

// ================= fp16 mma.sync GEMM (R8 config) + fused cnt blocks =================
#define HS 136
static constexpr int GSM_BYTES = (128 * HS + 64 * HS) * 2;  // 52224

__device__ __forceinline__ void mma16n8k16(float* c, const uint32_t* a, const uint32_t* b) {
    asm volatile(
        "mma.sync.aligned.m16n8k16.row.col.f32.f16.f16.f32 "
        "{%0,%1,%2,%3}, {%4,%5,%6,%7}, {%8,%9}, {%0,%1,%2,%3};"
        : "+f"(c[0]), "+f"(c[1]), "+f"(c[2]), "+f"(c[3])
        : "r"(a[0]), "r"(a[1]), "r"(a[2]), "r"(a[3]), "r"(b[0]), "r"(b[1]));
}

template <bool A32>
__global__ __launch_bounds__(256, 2)
void mma_gemm_kernel(const float* __restrict__ Ain, int M, int dout, int wrow0,
                     const void* __restrict__ ei, int E, int N, int gemmx) {
    if (blockIdx.x >= gemmx) {
        if (blockIdx.y == 0 && ei) {
            int base = ((blockIdx.x - gemmx) * 256 + threadIdx.x) * 4;
            if (base >= E) return;
            if (!g_is64 && (E & 3) == 0 && base + 4 <= E) {
                int4 d = *(const int4*)&((const int*)ei)[E + base];
                if (d.x >= 0 && d.x < N) atomicAdd(&g_deg[d.x], 1);
                if (d.y >= 0 && d.y < N) atomicAdd(&g_deg[d.y], 1);
                if (d.z >= 0 && d.z < N) atomicAdd(&g_deg[d.z], 1);
                if (d.w >= 0 && d.w < N) atomicAdd(&g_deg[d.w], 1);
            } else {
                for (int e = base; e < base + 4 && e < E; e++) {
                    int dst = g_is64 ? (int)((const long long*)ei)[E + e] : ((const int*)ei)[E + e];
                    if (dst >= 0 && dst < N) atomicAdd(&g_deg[dst], 1);
                }
            }
        }
        return;
    }

    extern __shared__ __half sh[];
    __half* As = sh;              // [128][HS]
    __half* Bs = sh + 128 * HS;   // [64][HS]
    const int tid = threadIdx.x;
    const int warp = tid >> 5;
    const int lane = tid & 31;
    const int warpM = warp & 3;
    const int warpN = warp >> 2;
    const int row0 = blockIdx.x * 128;
    const int col0 = blockIdx.y * 64;

    // ---- load A tile ----
    if (A32) {
        const float4* A4 = (const float4*)Ain;
        #pragma unroll
        for (int i = 0; i < 16; i++) {
            int idx = i * 256 + tid;
            int row = idx >> 5;
            int q   = idx & 31;
            float4 v = make_float4(0.f, 0.f, 0.f, 0.f);
            int gr = row0 + row;
            if (gr < M) v = A4[gr * 32 + q];
            __half2 h0 = __floats2half2_rn(v.x, v.y);
            __half2 h1 = __floats2half2_rn(v.z, v.w);
            *(uint2*)&As[row * HS + q * 4] =
                make_uint2(*(uint32_t*)&h0, *(uint32_t*)&h1);
        }
    } else {
        const uint4* H4 = (const uint4*)g_h;     // 8 halves per uint4
        #pragma unroll
        for (int i = 0; i < 8; i++) {
            int idx = i * 256 + tid;
            int row = idx >> 4;
            int q   = idx & 15;
            uint4 v = make_uint4(0u, 0u, 0u, 0u);
            int gr = row0 + row;
            if (gr < M) v = H4[gr * 16 + q];
            *(uint2*)&As[row * HS + q * 8]     = make_uint2(v.x, v.y);
            *(uint2*)&As[row * HS + q * 8 + 4] = make_uint2(v.z, v.w);
        }
    }
    // ---- load B tile (64 rows x 128 halves) ----
    {
        const uint4* W4 = (const uint4*)g_wcat;
        #pragma unroll
        for (int i = 0; i < 4; i++) {
            int idx = i * 256 + tid;
            int row = idx >> 4;
            int q   = idx & 15;
            uint4 v = W4[(wrow0 + col0 + row) * 16 + q];
            *(uint2*)&Bs[row * HS + q * 8]     = make_uint2(v.x, v.y);
            *(uint2*)&Bs[row * HS + q * 8 + 4] = make_uint2(v.z, v.w);
        }
    }
    __syncthreads();

    float c[2][4][4];
    #pragma unroll
    for (int mt = 0; mt < 2; mt++)
        #pragma unroll
        for (int nt = 0; nt < 4; nt++)
            #pragma unroll
            for (int j = 0; j < 4; j++) c[mt][nt][j] = 0.f;

    const int rA = warpM * 32 + (lane >> 2);
    const int nB = warpN * 32 + (lane >> 2);
    const int kh = (lane & 3) * 2;

    #pragma unroll
    for (int ks = 0; ks < 8; ks++) {
        const int k0 = ks * 16 + kh;
        uint32_t a[2][4], b[4][2];
        #pragma unroll
        for (int mt = 0; mt < 2; mt++) {
            int r = rA + mt * 16;
            a[mt][0] = *(const uint32_t*)&As[r * HS + k0];
            a[mt][1] = *(const uint32_t*)&As[(r + 8) * HS + k0];
            a[mt][2] = *(const uint32_t*)&As[r * HS + k0 + 8];
            a[mt][3] = *(const uint32_t*)&As[(r + 8) * HS + k0 + 8];
        }
        #pragma unroll
        for (int nt = 0; nt < 4; nt++) {
            int n = nB + nt * 8;
            b[nt][0] = *(const uint32_t*)&Bs[n * HS + k0];
            b[nt][1] = *(const uint32_t*)&Bs[n * HS + k0 + 8];
        }
        #pragma unroll
        for (int mt = 0; mt < 2; mt++)
            #pragma unroll
            for (int nt = 0; nt < 4; nt++)
                mma16n8k16(c[mt][nt], a[mt], b[nt]);
    }

    // ---- epilogue (both yl and yr stored fp16) ----
    const bool isl = (col0 < dout);
    #pragma unroll
    for (int mt = 0; mt < 2; mt++) {
        int r_lo = row0 + warpM * 32 + mt * 16 + (lane >> 2);
        #pragma unroll
        for (int nt = 0; nt < 4; nt++) {
            int col = col0 + warpN * 32 + nt * 8 + 2 * (lane & 3);
            __half* dst;
            int cc;
            if (isl) { dst = g_yl; cc = col; }
            else     { dst = g_yr; cc = col - dout; }
            if (r_lo < M)
                *(__half2*)&dst[r_lo * dout + cc] =
                    __floats2half2_rn(c[mt][nt][0], c[mt][nt][1]);
            if (r_lo + 8 < M)
                *(__half2*)&dst[(r_lo + 8) * dout + cc] =
                    __floats2half2_rn(c[mt][nt][2], c[mt][nt][3]);
        }
    }
}

// ================= fused aggregation epilogue (R8 unroll-2) =================
__device__ __forceinline__ void add4h(float* a, uint2 u) {
    __half2 h0 = *(__half2*)&u.x;
    __half2 h1 = *(__half2*)&u.y;
    float2 f0 = __half22float2(h0);
    float2 f1 = __half22float2(h1);
    a[0] += f0.x; a[1] += f0.y; a[2] += f1.x; a[3] += f1.y;
}

// OUT16: write g_h (fp16, with relu); else write outp (fp32, no relu)
template <int DOUT, bool OUT16>
__global__ void agg_kernel(const float* __restrict__ bl, const float* __restrict__ bs,
                           float* __restrict__ outp, int N) {
    const int HQ = DOUT / 4;
    int gt = blockIdx.x * blockDim.x + threadIdx.x;
    int n  = gt / HQ;
    int q  = gt & (HQ - 1);
    if (n >= N) return;

    int beg = g_rowptr[n];
    int end = g_rowptr[n + 1];
    const uint2* YL = (const uint2*)g_yl;

    float a0[4] = {0.f, 0.f, 0.f, 0.f};
    float a1[4] = {0.f, 0.f, 0.f, 0.f};
    int j = beg;
    for (; j + 1 < end; j += 2) {
        uint2 u0 = YL[g_srcs[j] * HQ + q];
        uint2 u1 = YL[g_srcs[j + 1] * HQ + q];
        add4h(a0, u0);
        add4h(a1, u1);
    }
    if (j < end) add4h(a0, YL[g_srcs[j] * HQ + q]);
    #pragma unroll
    for (int k = 0; k < 4; k++) a0[k] += a1[k];

    float inv = g_inv[n];
    uint2 yru = ((const uint2*)g_yr)[n * HQ + q];
    __half2 yh0 = *(__half2*)&yru.x;
    __half2 yh1 = *(__half2*)&yru.y;
    float2 yf0 = __half22float2(yh0);
    float2 yf1 = __half22float2(yh1);
    float4 b1 = ((const float4*)bl)[q];
    float4 b2 = ((const float4*)bs)[q];
    float4 o;
    o.x = fmaf(a0[0], inv, yf0.x) + b1.x + b2.x;
    o.y = fmaf(a0[1], inv, yf0.y) + b1.y + b2.y;
    o.z = fmaf(a0[2], inv, yf1.x) + b1.z + b2.z;
    o.w = fmaf(a0[3], inv, yf1.y) + b1.w + b2.w;
    if (OUT16) {
        o.x = fmaxf(o.x, 0.f); o.y = fmaxf(o.y, 0.f);
        o.z = fmaxf(o.z, 0.f); o.w = fmaxf(o.w, 0.f);
        __half2 h0 = __floats2half2_rn(o.x, o.y);
        __half2 h1 = __floats2half2_rn(o.z, o.w);
        *(uint2*)&g_h[n * DOUT + q * 4] = make_uint2(*(uint32_t*)&h0, *(uint32_t*)&h1);
    } else {
        ((float4*)outp)[n * HQ + q] = o;
    }
}

// ================= host launch =================
extern "C" void kernel_launch(void* const* d_in, const int* in_sizes, int n_in,
                              void* d_out, int out_size) {
    const float* x  = (const float*)d_in[0];
    const void*  ei = d_in[1];
    const float* Wl[3] = {(const float*)d_in[4],  (const float*)d_in[9],  (const float*)d_in[14]};
    const float* bl[3] = {(const float*)d_in[5],  (const float*)d_in[10], (const float*)d_in[15]};
    const float* Wr[3] = {(const float*)d_in[6],  (const float*)d_in[11], (const float*)d_in[16]};
    const float* Ws[3] = {(const float*)d_in[7],  (const float*)d_in[12], (const float*)d_in[17]};
    const float* bs[3] = {(const float*)d_in[8],  (const float*)d_in[13], (const float*)d_in[18]};

    int N = in_sizes[0] / 128;
    int E = in_sizes[1] / 2;

    cudaFuncSetAttribute(mma_gemm_kernel<true>,  cudaFuncAttributeMaxDynamicSharedMemorySize, GSM_BYTES);
    cudaFuncSetAttribute(mma_gemm_kernel<false>, cudaFuncAttributeMaxDynamicSharedMemorySize, GSM_BYTES);

    // ---- setup (wcat + zero_deg + probe) ----
    int setup_grid = WCAT_BLOCKS + (N + 255) / 256 + 1;
    setup_kernel<<<setup_grid, 256>>>(Wl[0], Wr[0], Ws[0], Wl[1], Wr[1], Ws[1],
                                      Wl[2], Wr[2], Ws[2], ei, E, N);

    const int douts[3]  = {128, 128, 64};
    const int wrow0s[3] = {0, 256, 512};
    int gx = (N + 127) / 128;
    int cntb = (E / 4 + 255) / 256;

    // ---- layer 0 GEMM with fused cnt blocks ----
    {
        dim3 gg(gx + cntb, (2 * douts[0]) / 64);
        mma_gemm_kernel<true><<<gg, 256, GSM_BYTES>>>(x, N, douts[0], wrow0s[0],
                                                      ei, E, N, gx);
    }
    // ---- scan + fill ----
    int nb = (N + SCAN_BLK - 1) / SCAN_BLK;
    scan1_kernel<<<nb, SCAN_BLK>>>(N);
    scan2_kernel<<<1, SCAN_BLK>>>(nb);
    scan3_kernel<<<nb, SCAN_BLK>>>(N);
    fill_kernel<<<(E / 4 + 255) / 256, 256>>>(ei, E, N);

    // ---- layer 0 agg, then layers 1..2 ----
    agg_kernel<128, true><<<(N * 32 + 255) / 256, 256>>>(bl[0], bs[0], nullptr, N);

    for (int L = 1; L < 3; L++) {
        int dout = douts[L];
        dim3 gg(gx, (2 * dout) / 64);
        mma_gemm_kernel<false><<<gg, 256, GSM_BYTES>>>(nullptr, N, dout, wrow0s[L],
                                                       nullptr, 0, N, gx);
        int threads = N * (dout / 4);
        if (L < 2)
            agg_kernel<128, true><<<(threads + 255) / 256, 256>>>(bl[L], bs[L], nullptr, N);
        else
            agg_kernel<64, false><<<(threads + 255) / 256, 256>>>(bl[L], bs[L], (float*)d_out, N);
    }
}